// round 2
// baseline (speedup 1.0000x reference)
#include <cuda_runtime.h>
#include <cstdint>
#include <math.h>

// ---------------------------------------------------------------------------
// TextEncoder (SRU, 4 layers) on GB300.
// Pipeline: gather -> [GEMM -> scan] x4 -> L2 normalize.
// GEMMs run as TF32 mma.sync (m16n8k8) with RNA conversion on smem store.
// ---------------------------------------------------------------------------

#define L_SEQ 256
#define BATCH 32
#define KDIM  620
#define DDIM  2400
#define MROWS (L_SEQ * BATCH)   // 8192
#define N0    (4 * DDIM)        // 9600
#define N123  (3 * DDIM)        // 7200

// -------------------- scratch (static device allocations) ------------------
__device__ float g_X0[MROWS * KDIM];        // gathered embeddings
__device__ float g_U [MROWS * N0];          // GEMM output (max size, reused)
__device__ float g_H0[MROWS * DDIM];        // layer activations ping
__device__ float g_H1[MROWS * DDIM];        // layer activations pong

// ------------------------------ GEMM --------------------------------------
#define BM 128
#define BN 128
#define BK 32
#define A_STR 36     // BK + 4 pad  -> conflict-free frag LDS and STS.128
#define B_STR 132    // BN + 4 pad
#define SMEM_FLOATS (2 * BM * A_STR + 2 * BK * B_STR)   // 17664 floats = 70656 B

__device__ __forceinline__ float cvt_tf32(float x) {
    uint32_t u;
    asm volatile("cvt.rna.tf32.f32 %0, %1;" : "=r"(u) : "f"(x));
    return __uint_as_float(u);
}

__device__ __forceinline__ void mma8(float* c, const uint32_t* a, const uint32_t* b) {
    asm volatile(
        "mma.sync.aligned.m16n8k8.row.col.f32.tf32.tf32.f32 "
        "{%0,%1,%2,%3}, {%4,%5,%6,%7}, {%8,%9}, {%0,%1,%2,%3};\n"
        : "+f"(c[0]), "+f"(c[1]), "+f"(c[2]), "+f"(c[3])
        : "r"(a[0]), "r"(a[1]), "r"(a[2]), "r"(a[3]),
          "r"(b[0]), "r"(b[1]));
}

// C[M,N] = A[M,K] (row-major) * W[K,N] (row-major), TF32 tensor core path.
// 128 threads = 4 warps (2x2), each warp owns a 64x64 tile of the 128x128 CTA tile.
__global__ void __launch_bounds__(128, 2)
gemm_tf32(const float* __restrict__ A, const float* __restrict__ W,
          float* __restrict__ C, int M, int K, int N)
{
    extern __shared__ float sm[];
    float* As = sm;                       // [2][BM][A_STR]
    float* Bs = sm + 2 * BM * A_STR;      // [2][BK][B_STR]

    const int tid  = threadIdx.x;
    const int warp = tid >> 5, lane = tid & 31;
    const int wm = warp >> 1, wn = warp & 1;   // warp grid 2x2
    const int g = lane >> 2, t = lane & 3;     // groupID / threadID_in_group

    const int bm = blockIdx.y * BM;
    const int bn = blockIdx.x * BN;
    const bool nfull = (bn + BN) <= N;

    float acc[4][8][4];
    #pragma unroll
    for (int i = 0; i < 4; i++)
        #pragma unroll
        for (int j = 0; j < 8; j++)
            #pragma unroll
            for (int q = 0; q < 4; q++) acc[i][j][q] = 0.f;

    // global->reg staging indices
    const int a_row = tid >> 3;   // 0..15 (8 float4 per 32-float row)
    const int a_c4  = tid & 7;
    const int b_row = tid >> 5;   // 0..3  (32 float4 per 128-float row)
    const int b_c4  = tid & 31;

    const int ktiles = (K + BK - 1) / BK;

    float4 ra[8], rb[8];

    auto ldg_tile = [&](int kt) {
        const int k0 = kt * BK;
        const bool kfull = (k0 + BK) <= K;
        #pragma unroll
        for (int i = 0; i < 8; i++) {
            int row = a_row + i * 16;
            const float* ap = A + (size_t)(bm + row) * K + k0 + a_c4 * 4;
            if (kfull) {
                ra[i] = *(const float4*)ap;
            } else {
                int kk = k0 + a_c4 * 4;
                ra[i].x = (kk + 0 < K) ? ap[0] : 0.f;
                ra[i].y = (kk + 1 < K) ? ap[1] : 0.f;
                ra[i].z = (kk + 2 < K) ? ap[2] : 0.f;
                ra[i].w = (kk + 3 < K) ? ap[3] : 0.f;
            }
        }
        #pragma unroll
        for (int i = 0; i < 8; i++) {
            int gk = k0 + b_row + i * 4;
            int gn = bn + b_c4 * 4;
            float4 v = make_float4(0.f, 0.f, 0.f, 0.f);
            if (gk < K) {
                const float* bp = W + (size_t)gk * N + gn;
                if (nfull) {
                    v = *(const float4*)bp;
                } else {
                    if (gn + 0 < N) v.x = bp[0];
                    if (gn + 1 < N) v.y = bp[1];
                    if (gn + 2 < N) v.z = bp[2];
                    if (gn + 3 < N) v.w = bp[3];
                }
            }
            rb[i] = v;
        }
    };

    auto sts_tile = [&](int buf) {
        #pragma unroll
        for (int i = 0; i < 8; i++) {
            int row = a_row + i * 16;
            float4 v = ra[i];
            v.x = cvt_tf32(v.x); v.y = cvt_tf32(v.y);
            v.z = cvt_tf32(v.z); v.w = cvt_tf32(v.w);
            *(float4*)&As[buf * (BM * A_STR) + row * A_STR + a_c4 * 4] = v;
        }
        #pragma unroll
        for (int i = 0; i < 8; i++) {
            int krow = b_row + i * 4;
            float4 v = rb[i];
            v.x = cvt_tf32(v.x); v.y = cvt_tf32(v.y);
            v.z = cvt_tf32(v.z); v.w = cvt_tf32(v.w);
            *(float4*)&Bs[buf * (BK * B_STR) + krow * B_STR + b_c4 * 4] = v;
        }
    };

    ldg_tile(0);
    sts_tile(0);
    __syncthreads();

    int buf = 0;
    for (int kt = 0; kt < ktiles; kt++) {
        if (kt + 1 < ktiles) ldg_tile(kt + 1);

        #pragma unroll
        for (int ks = 0; ks < 4; ks++) {
            uint32_t af[4][4], bfr[8][2];
            const float* abase = &As[buf * (BM * A_STR)];
            const float* bbase = &Bs[buf * (BK * B_STR)];
            #pragma unroll
            for (int mf = 0; mf < 4; mf++) {
                int r = wm * 64 + mf * 16;
                af[mf][0] = __float_as_uint(abase[(r + g    ) * A_STR + ks * 8 + t    ]);
                af[mf][1] = __float_as_uint(abase[(r + g + 8) * A_STR + ks * 8 + t    ]);
                af[mf][2] = __float_as_uint(abase[(r + g    ) * A_STR + ks * 8 + t + 4]);
                af[mf][3] = __float_as_uint(abase[(r + g + 8) * A_STR + ks * 8 + t + 4]);
            }
            #pragma unroll
            for (int nf = 0; nf < 8; nf++) {
                int cidx = wn * 64 + nf * 8 + g;
                bfr[nf][0] = __float_as_uint(bbase[(ks * 8 + t    ) * B_STR + cidx]);
                bfr[nf][1] = __float_as_uint(bbase[(ks * 8 + t + 4) * B_STR + cidx]);
            }
            #pragma unroll
            for (int mf = 0; mf < 4; mf++)
                #pragma unroll
                for (int nf = 0; nf < 8; nf++)
                    mma8(acc[mf][nf], af[mf], bfr[nf]);
        }

        if (kt + 1 < ktiles) {
            sts_tile(buf ^ 1);
            __syncthreads();
            buf ^= 1;
        }
    }

    // epilogue: fragment layout row = {g, g+8}, col = 2t, 2t+1
    #pragma unroll
    for (int mf = 0; mf < 4; mf++) {
        #pragma unroll
        for (int nf = 0; nf < 8; nf++) {
            int row0 = bm + wm * 64 + mf * 16 + g;
            int col  = bn + wn * 64 + nf * 8 + 2 * t;
            if (col < N) {
                float2 v0 = make_float2(acc[mf][nf][0], acc[mf][nf][1]);
                float2 v1 = make_float2(acc[mf][nf][2], acc[mf][nf][3]);
                *(float2*)&C[(size_t)row0 * N + col]       = v0;
                *(float2*)&C[(size_t)(row0 + 8) * N + col] = v1;
            }
        }
    }
}

// --------------------------- embedding gather ------------------------------
__global__ void gather_k(const int* __restrict__ tok, const float* __restrict__ emb,
                         float* __restrict__ X)
{
    int i = blockIdx.x * 256 + threadIdx.x;
    if (i < MROWS * KDIM) {
        int m = i / KDIM;
        int k = i - m * KDIM;
        X[i] = emb[(size_t)tok[m] * KDIM + k];
    }
}

// ------------------------------- SRU scans ---------------------------------
__device__ __forceinline__ float sigm(float x) { return 1.f / (1.f + __expf(-x)); }

// Layer 0: U has 4 planes [z, f, r, skip]; skip comes from U itself.
__global__ void scan4_k(const float* __restrict__ U, const float* __restrict__ bias,
                        float* __restrict__ H)
{
    int idx = blockIdx.x * blockDim.x + threadIdx.x;
    if (idx >= BATCH * DDIM) return;
    int b = idx / DDIM, d = idx - b * DDIM;
    float bf = bias[d], br = bias[DDIM + d];
    float c = 0.f;
    for (int l = 0; l < L_SEQ; l++) {
        const float* row = U + ((size_t)(l * BATCH + b) * 4) * DDIM + d;
        float z = row[0];
        float f = sigm(row[DDIM] + bf);
        float r = sigm(row[2 * DDIM] + br);
        float s = row[3 * DDIM];
        c = f * c + (1.f - f) * z;
        H[(size_t)(l * BATCH + b) * DDIM + d] = r * tanhf(c) + (1.f - r) * s;
    }
}

// Layers 1-3: U has 3 planes [z, f, r]; skip comes from layer input Xin.
__global__ void scan3_k(const float* __restrict__ U, const float* __restrict__ Xin,
                        const float* __restrict__ bias, float* __restrict__ H)
{
    int idx = blockIdx.x * blockDim.x + threadIdx.x;
    if (idx >= BATCH * DDIM) return;
    int b = idx / DDIM, d = idx - b * DDIM;
    float bf = bias[d], br = bias[DDIM + d];
    float c = 0.f;
    for (int l = 0; l < L_SEQ; l++) {
        size_t m = (size_t)(l * BATCH + b);
        const float* row = U + m * 3 * DDIM + d;
        float z = row[0];
        float f = sigm(row[DDIM] + bf);
        float r = sigm(row[2 * DDIM] + br);
        float s = Xin[m * DDIM + d];
        c = f * c + (1.f - f) * z;
        H[m * DDIM + d] = r * tanhf(c) + (1.f - r) * s;
    }
}

// ------------------------------ L2 normalize -------------------------------
__global__ void l2norm_k(const float* __restrict__ X, float* __restrict__ out)
{
    int row = blockIdx.x;   // 0..MROWS-1
    const float* x = X + (size_t)row * DDIM;
    float s = 0.f;
    for (int d = threadIdx.x; d < DDIM; d += blockDim.x) {
        float v = x[d];
        s += v * v;
    }
    __shared__ float sh[32];
    #pragma unroll
    for (int o = 16; o; o >>= 1) s += __shfl_xor_sync(0xffffffffu, s, o);
    int lane = threadIdx.x & 31, w = threadIdx.x >> 5;
    if (lane == 0) sh[w] = s;
    __syncthreads();
    if (w == 0) {
        s = (lane < (int)(blockDim.x >> 5)) ? sh[lane] : 0.f;
        #pragma unroll
        for (int o = 16; o; o >>= 1) s += __shfl_xor_sync(0xffffffffu, s, o);
        if (lane == 0) sh[0] = rsqrtf(s);
    }
    __syncthreads();
    float inv = sh[0];
    for (int d = threadIdx.x; d < DDIM; d += blockDim.x)
        out[(size_t)row * DDIM + d] = x[d] * inv;
}

// ------------------------------- launcher ----------------------------------
extern "C" void kernel_launch(void* const* d_in, const int* in_sizes, int n_in,
                              void* d_out, int out_size)
{
    const int*   tokens = (const int*)  d_in[0];
    const float* emb    = (const float*)d_in[1];
    const float* W0     = (const float*)d_in[2];
    const float* b0     = (const float*)d_in[3];
    const float* W1     = (const float*)d_in[4];
    const float* b1     = (const float*)d_in[5];
    const float* W2     = (const float*)d_in[6];
    const float* b2     = (const float*)d_in[7];
    const float* W3     = (const float*)d_in[8];
    const float* b3     = (const float*)d_in[9];
    float* out = (float*)d_out;

    float *X0, *U, *H0, *H1;
    cudaGetSymbolAddress((void**)&X0, g_X0);
    cudaGetSymbolAddress((void**)&U,  g_U);
    cudaGetSymbolAddress((void**)&H0, g_H0);
    cudaGetSymbolAddress((void**)&H1, g_H1);

    const size_t shmem = SMEM_FLOATS * sizeof(float);
    cudaFuncSetAttribute(gemm_tf32, cudaFuncAttributeMaxDynamicSharedMemorySize,
                         (int)shmem);

    // Embedding gather
    {
        int tot = MROWS * KDIM;
        gather_k<<<(tot + 255) / 256, 256>>>(tokens, emb, X0);
    }

    const int scan_blocks = (BATCH * DDIM + 255) / 256;

    // Layer 0: K=620, N=9600 (4 planes)
    gemm_tf32<<<dim3(N0 / BN, MROWS / BM), 128, shmem>>>(X0, W0, U, MROWS, KDIM, N0);
    scan4_k<<<scan_blocks, 256>>>(U, b0, H0);

    // Layer 1
    gemm_tf32<<<dim3((N123 + BN - 1) / BN, MROWS / BM), 128, shmem>>>(H0, W1, U, MROWS, DDIM, N123);
    scan3_k<<<scan_blocks, 256>>>(U, H0, b1, H1);

    // Layer 2
    gemm_tf32<<<dim3((N123 + BN - 1) / BN, MROWS / BM), 128, shmem>>>(H1, W2, U, MROWS, DDIM, N123);
    scan3_k<<<scan_blocks, 256>>>(U, H1, b2, H0);

    // Layer 3
    gemm_tf32<<<dim3((N123 + BN - 1) / BN, MROWS / BM), 128, shmem>>>(H0, W3, U, MROWS, DDIM, N123);
    scan3_k<<<scan_blocks, 256>>>(U, H0, b3, H1);

    // Final L2 normalization -> d_out
    l2norm_k<<<MROWS, 256>>>(H1, out);
}

// round 4
// speedup vs baseline: 1.0419x; 1.0419x over previous
#include <cuda_runtime.h>
#include <cstdint>
#include <math.h>

// ---------------------------------------------------------------------------
// TextEncoder (SRU, 4 layers) on GB300.
// Harness builds via compute_103 (no 'a') -> tcgen05 unavailable.
// GEMM: legacy mma.sync m16n8k8 TF32, cp.async 3-stage pipeline,
// all GEMM inputs pre-rounded to TF32-RNA so HMMA truncation is exact.
// ---------------------------------------------------------------------------

#define L_SEQ 256
#define BATCH 32
#define KDIM  620
#define DDIM  2400
#define MROWS (L_SEQ * BATCH)   // 8192
#define N0    (4 * DDIM)        // 9600
#define N123  (3 * DDIM)        // 7200

// ------------------------------ scratch ------------------------------------
__device__ __align__(1024) float g_X0[MROWS * KDIM];
__device__ __align__(1024) float g_U [MROWS * N0];
__device__ __align__(1024) float g_H0[MROWS * DDIM];
__device__ __align__(1024) float g_H1[MROWS * DDIM];
__device__ __align__(1024) float g_WT0[(size_t)N0 * KDIM];     // [9600,620] K-major
__device__ __align__(1024) float g_WT1[(size_t)N123 * DDIM];   // [7200,2400]
__device__ __align__(1024) float g_WT2[(size_t)N123 * DDIM];
__device__ __align__(1024) float g_WT3[(size_t)N123 * DDIM];

// ------------------------------ helpers ------------------------------------
__device__ __forceinline__ float cvt_tf32(float x) {
    uint32_t u;
    asm volatile("cvt.rna.tf32.f32 %0, %1;" : "=r"(u) : "f"(x));
    return __uint_as_float(u);
}

__device__ __forceinline__ uint32_t smem_u32(const void* p) {
    uint32_t a;
    asm("{ .reg .u64 t; cvta.to.shared.u64 t, %1; cvt.u32.u64 %0, t; }"
        : "=r"(a) : "l"(p));
    return a;
}

__device__ __forceinline__ void cp16(uint32_t dst, const void* src, int szbytes) {
    asm volatile("cp.async.cg.shared.global [%0], [%1], 16, %2;"
                 :: "r"(dst), "l"(src), "r"(szbytes) : "memory");
}
#define CP_COMMIT() asm volatile("cp.async.commit_group;" ::: "memory")
#define CP_WAIT1()  asm volatile("cp.async.wait_group 1;"  ::: "memory")

__device__ __forceinline__ void mma8(float* c, const uint32_t* a, const uint32_t* b) {
    asm volatile(
        "mma.sync.aligned.m16n8k8.row.col.f32.tf32.tf32.f32 "
        "{%0,%1,%2,%3}, {%4,%5,%6,%7}, {%8,%9}, {%0,%1,%2,%3};\n"
        : "+f"(c[0]), "+f"(c[1]), "+f"(c[2]), "+f"(c[3])
        : "r"(a[0]), "r"(a[1]), "r"(a[2]), "r"(a[3]),
          "r"(b[0]), "r"(b[1]));
}

// ------------------------------ GEMM ---------------------------------------
// C[M,N] = A[M,K] * WT[N,K]^T, both K-major fp32 storage holding tf32 values.
// CTA: 128(M) x 96(N), BK=32. 256 threads = 8 warps, warp grid 4(m) x 2(n),
// warp tile 32x48. 3-stage cp.async pipeline.
#define BM 128
#define BN 96
#define BK 32
#define AS_STR 36                        // 32 + 4 pad (floats)
#define A_BYTES (BM * AS_STR * 4)        // 18432
#define B_BYTES (BN * AS_STR * 4)        // 13824
#define STAGE_BYTES (A_BYTES + B_BYTES)  // 32256
#define NSTAGE 3
#define GEMM_SMEM (NSTAGE * STAGE_BYTES) // 96768

__global__ void __launch_bounds__(256, 2)
gemm_tf32(const float* __restrict__ A, const float* __restrict__ BT,
          float* __restrict__ C, int Kdim, int Ndim, int KT)
{
    extern __shared__ char smraw[];
    const uint32_t sbase = smem_u32(smraw);

    const int tid  = threadIdx.x;
    const int warp = tid >> 5, lane = tid & 31;
    const int wm = warp & 3, wn = warp >> 2;      // 4 x 2 warp grid
    const int g = lane >> 2, t = lane & 3;

    const int bm = blockIdx.y * BM;
    const int bn = blockIdx.x * BN;

    float acc[2][6][4];
    #pragma unroll
    for (int i = 0; i < 2; i++)
        #pragma unroll
        for (int j = 0; j < 6; j++)
            #pragma unroll
            for (int q = 0; q < 4; q++) acc[i][j][q] = 0.f;

    // stage loader: 1024 A-chunks + 768 B-chunks of 16B, 256 threads
    auto load_stage = [&](int kt, int st) {
        const int k0 = kt * BK;
        const uint32_t sA = sbase + st * STAGE_BYTES;
        const uint32_t sB = sA + A_BYTES;
        #pragma unroll
        for (int i = 0; i < 4; i++) {
            int c = tid + i * 256;
            int row = c >> 3, cc = c & 7;
            int k = k0 + cc * 4;
            int rem = Kdim - k;
            int sz = rem >= 4 ? 16 : (rem > 0 ? rem * 4 : 0);
            int kc = (k < Kdim) ? k : 0;
            cp16(sA + row * (AS_STR * 4) + cc * 16,
                 A + (size_t)(bm + row) * Kdim + kc, sz);
        }
        #pragma unroll
        for (int i = 0; i < 3; i++) {
            int c = tid + i * 256;
            int row = c >> 3, cc = c & 7;
            int k = k0 + cc * 4;
            int rem = Kdim - k;
            int sz = rem >= 4 ? 16 : (rem > 0 ? rem * 4 : 0);
            int kc = (k < Kdim) ? k : 0;
            cp16(sB + row * (AS_STR * 4) + cc * 16,
                 BT + (size_t)(bn + row) * Kdim + kc, sz);
        }
    };

    load_stage(0, 0); CP_COMMIT();
    load_stage(1, 1); CP_COMMIT();

    for (int kt = 0; kt < KT; kt++) {
        CP_WAIT1();                 // stage kt resident
        __syncthreads();            // also: all threads done computing kt-1
        if (kt + 2 < KT) load_stage(kt + 2, (kt + 2) % NSTAGE);
        CP_COMMIT();                // commit every iter (keeps group count uniform)

        const float* As = (const float*)(smraw + (kt % NSTAGE) * STAGE_BYTES);
        const float* Bs = As + BM * AS_STR;

        #pragma unroll
        for (int ks = 0; ks < 4; ks++) {
            uint32_t af[2][4], bf[6][2];
            #pragma unroll
            for (int mf = 0; mf < 2; mf++) {
                const float* ap = As + (wm * 32 + mf * 16 + g) * AS_STR + ks * 8 + t;
                af[mf][0] = __float_as_uint(ap[0]);
                af[mf][1] = __float_as_uint(ap[8 * AS_STR]);
                af[mf][2] = __float_as_uint(ap[4]);
                af[mf][3] = __float_as_uint(ap[8 * AS_STR + 4]);
            }
            #pragma unroll
            for (int nf = 0; nf < 6; nf++) {
                const float* bp = Bs + (wn * 48 + nf * 8 + g) * AS_STR + ks * 8 + t;
                bf[nf][0] = __float_as_uint(bp[0]);
                bf[nf][1] = __float_as_uint(bp[4]);
            }
            #pragma unroll
            for (int mf = 0; mf < 2; mf++)
                #pragma unroll
                for (int nf = 0; nf < 6; nf++)
                    mma8(acc[mf][nf], af[mf], bf[nf]);
        }
    }

    // epilogue: c0,c1 -> (row g, cols 2t,2t+1); c2,c3 -> row g+8
    #pragma unroll
    for (int mf = 0; mf < 2; mf++) {
        #pragma unroll
        for (int nf = 0; nf < 6; nf++) {
            int row0 = bm + wm * 32 + mf * 16 + g;
            int col  = bn + wn * 48 + nf * 8 + 2 * t;
            *(float2*)&C[(size_t)row0 * Ndim + col] =
                make_float2(acc[mf][nf][0], acc[mf][nf][1]);
            *(float2*)&C[(size_t)(row0 + 8) * Ndim + col] =
                make_float2(acc[mf][nf][2], acc[mf][nf][3]);
        }
    }
}

// --------------------------- W transpose (+ tf32 round) --------------------
__global__ void transpose_k(const float* __restrict__ W, float* __restrict__ WT,
                            int K, int N)
{
    __shared__ float t[32][33];
    int kb = blockIdx.y * 32, nb = blockIdx.x * 32;
    #pragma unroll
    for (int i = 0; i < 32; i += 8) {
        int k = kb + threadIdx.y + i, n = nb + threadIdx.x;
        if (k < K && n < N) t[threadIdx.y + i][threadIdx.x] = W[(size_t)k * N + n];
    }
    __syncthreads();
    #pragma unroll
    for (int i = 0; i < 32; i += 8) {
        int n = nb + threadIdx.y + i, k = kb + threadIdx.x;
        if (n < N && k < K)
            WT[(size_t)n * K + k] = cvt_tf32(t[threadIdx.x][threadIdx.y + i]);
    }
}

// --------------------------- embedding gather ------------------------------
__global__ void gather_k(const int* __restrict__ tok, const float* __restrict__ emb,
                         float* __restrict__ X)
{
    int i = blockIdx.x * 256 + threadIdx.x;
    if (i < MROWS * KDIM) {
        int m = i / KDIM;
        int k = i - m * KDIM;
        X[i] = cvt_tf32(emb[(size_t)tok[m] * KDIM + k]);
    }
}

// ------------------------------- SRU scans ---------------------------------
__device__ __forceinline__ float sigm(float x) { return 1.f / (1.f + __expf(-x)); }

__global__ void scan4_k(const float* __restrict__ U, const float* __restrict__ bias,
                        float* __restrict__ H)
{
    int idx = blockIdx.x * blockDim.x + threadIdx.x;
    if (idx >= BATCH * DDIM) return;
    int b = idx / DDIM, d = idx - b * DDIM;
    float bf = bias[d], br = bias[DDIM + d];
    float c = 0.f;
    for (int l = 0; l < L_SEQ; l++) {
        const float* row = U + ((size_t)(l * BATCH + b) * 4) * DDIM + d;
        float z = row[0];
        float f = sigm(row[DDIM] + bf);
        float r = sigm(row[2 * DDIM] + br);
        float s = row[3 * DDIM];
        c = f * c + (1.f - f) * z;
        H[(size_t)(l * BATCH + b) * DDIM + d] = cvt_tf32(r * tanhf(c) + (1.f - r) * s);
    }
}

__global__ void scan3_k(const float* __restrict__ U, const float* __restrict__ Xin,
                        const float* __restrict__ bias, float* __restrict__ H)
{
    int idx = blockIdx.x * blockDim.x + threadIdx.x;
    if (idx >= BATCH * DDIM) return;
    int b = idx / DDIM, d = idx - b * DDIM;
    float bf = bias[d], br = bias[DDIM + d];
    float c = 0.f;
    for (int l = 0; l < L_SEQ; l++) {
        size_t m = (size_t)(l * BATCH + b);
        const float* row = U + m * 3 * DDIM + d;
        float z = row[0];
        float f = sigm(row[DDIM] + bf);
        float r = sigm(row[2 * DDIM] + br);
        float s = Xin[m * DDIM + d];
        c = f * c + (1.f - f) * z;
        H[m * DDIM + d] = cvt_tf32(r * tanhf(c) + (1.f - r) * s);
    }
}

// ------------------------------ L2 normalize -------------------------------
__global__ void l2norm_k(const float* __restrict__ X, float* __restrict__ out)
{
    int row = blockIdx.x;
    const float* x = X + (size_t)row * DDIM;
    float s = 0.f;
    for (int d = threadIdx.x; d < DDIM; d += blockDim.x) {
        float v = x[d];
        s += v * v;
    }
    __shared__ float sh[32];
    #pragma unroll
    for (int o = 16; o; o >>= 1) s += __shfl_xor_sync(0xffffffffu, s, o);
    int lane = threadIdx.x & 31, w = threadIdx.x >> 5;
    if (lane == 0) sh[w] = s;
    __syncthreads();
    if (w == 0) {
        s = (lane < (int)(blockDim.x >> 5)) ? sh[lane] : 0.f;
        #pragma unroll
        for (int o = 16; o; o >>= 1) s += __shfl_xor_sync(0xffffffffu, s, o);
        if (lane == 0) sh[0] = rsqrtf(s);
    }
    __syncthreads();
    float inv = sh[0];
    for (int d = threadIdx.x; d < DDIM; d += blockDim.x)
        out[(size_t)row * DDIM + d] = x[d] * inv;
}

// ------------------------------- launcher ----------------------------------
extern "C" void kernel_launch(void* const* d_in, const int* in_sizes, int n_in,
                              void* d_out, int out_size)
{
    const int*   tokens = (const int*)  d_in[0];
    const float* emb    = (const float*)d_in[1];
    const float* W0     = (const float*)d_in[2];
    const float* b0     = (const float*)d_in[3];
    const float* W1     = (const float*)d_in[4];
    const float* b1     = (const float*)d_in[5];
    const float* W2     = (const float*)d_in[6];
    const float* b2     = (const float*)d_in[7];
    const float* W3     = (const float*)d_in[8];
    const float* b3     = (const float*)d_in[9];
    float* out = (float*)d_out;

    float *X0, *U, *H0, *H1, *WT0, *WT1, *WT2, *WT3;
    cudaGetSymbolAddress((void**)&X0,  g_X0);
    cudaGetSymbolAddress((void**)&U,   g_U);
    cudaGetSymbolAddress((void**)&H0,  g_H0);
    cudaGetSymbolAddress((void**)&H1,  g_H1);
    cudaGetSymbolAddress((void**)&WT0, g_WT0);
    cudaGetSymbolAddress((void**)&WT1, g_WT1);
    cudaGetSymbolAddress((void**)&WT2, g_WT2);
    cudaGetSymbolAddress((void**)&WT3, g_WT3);

    cudaFuncSetAttribute(gemm_tf32, cudaFuncAttributeMaxDynamicSharedMemorySize,
                         GEMM_SMEM);

    // W transposes (K-major, tf32-rounded)
    {
        dim3 blk(32, 8);
        transpose_k<<<dim3((N0 + 31) / 32, (KDIM + 31) / 32), blk>>>(W0, WT0, KDIM, N0);
        transpose_k<<<dim3((N123 + 31) / 32, (DDIM + 31) / 32), blk>>>(W1, WT1, DDIM, N123);
        transpose_k<<<dim3((N123 + 31) / 32, (DDIM + 31) / 32), blk>>>(W2, WT2, DDIM, N123);
        transpose_k<<<dim3((N123 + 31) / 32, (DDIM + 31) / 32), blk>>>(W3, WT3, DDIM, N123);
    }

    // Embedding gather (tf32-rounded)
    gather_k<<<(MROWS * KDIM + 255) / 256, 256>>>(tokens, emb, X0);

    const int scan_blocks = (BATCH * DDIM + 255) / 256;
    const int KT0 = (KDIM + BK - 1) / BK;   // 20
    const int KT1 = DDIM / BK;              // 75

    // Layer 0: K=620, N=9600
    gemm_tf32<<<dim3(N0 / BN, MROWS / BM), 256, GEMM_SMEM>>>(X0, WT0, U, KDIM, N0, KT0);
    scan4_k<<<scan_blocks, 256>>>(U, b0, H0);

    // Layer 1
    gemm_tf32<<<dim3(N123 / BN, MROWS / BM), 256, GEMM_SMEM>>>(H0, WT1, U, DDIM, N123, KT1);
    scan3_k<<<scan_blocks, 256>>>(U, H0, b1, H1);

    // Layer 2
    gemm_tf32<<<dim3(N123 / BN, MROWS / BM), 256, GEMM_SMEM>>>(H1, WT2, U, DDIM, N123, KT1);
    scan3_k<<<scan_blocks, 256>>>(U, H1, b2, H0);

    // Layer 3
    gemm_tf32<<<dim3(N123 / BN, MROWS / BM), 256, GEMM_SMEM>>>(H0, WT3, U, DDIM, N123, KT1);
    scan3_k<<<scan_blocks, 256>>>(U, H0, b3, H1);

    // Final L2 normalization -> d_out
    l2norm_k<<<MROWS, 256>>>(H1, out);
}

// round 6
// speedup vs baseline: 1.2586x; 1.2079x over previous
#include <cuda_runtime.h>
#include <cuda_fp16.h>
#include <cstdint>
#include <math.h>

// ---------------------------------------------------------------------------
// TextEncoder (SRU, 4 layers) on GB300.
// compute_103 target -> no tcgen05. GEMM: legacy mma.sync m16n8k16 FP16
// (fp32 accum). fp16 mantissa == tf32 mantissa (10 bits) -> same numerics,
// 2x tensor rate, half the smem/L2/DRAM traffic.
// ---------------------------------------------------------------------------

#define L_SEQ 256
#define BATCH 32
#define KDIM  620
#define KP0   640               // padded K for layer 0 (16B-aligned rows)
#define DDIM  2400
#define MROWS (L_SEQ * BATCH)   // 8192
#define N0    (4 * DDIM)        // 9600
#define N123  (3 * DDIM)        // 7200

// ------------------------------ scratch ------------------------------------
__device__ __align__(1024) __half g_X0h[MROWS * KP0];
__device__ __align__(1024) __half g_U  [MROWS * N0];
__device__ __align__(1024) __half g_H0h[MROWS * DDIM];
__device__ __align__(1024) __half g_H1h[MROWS * DDIM];
__device__ __align__(1024) __half g_WT0[(size_t)N0 * KP0];
__device__ __align__(1024) __half g_WT1[(size_t)N123 * DDIM];
__device__ __align__(1024) __half g_WT2[(size_t)N123 * DDIM];
__device__ __align__(1024) __half g_WT3[(size_t)N123 * DDIM];

// ------------------------------ helpers ------------------------------------
__device__ __forceinline__ uint32_t smem_u32(const void* p) {
    uint32_t a;
    asm("{ .reg .u64 t; cvta.to.shared.u64 t, %1; cvt.u32.u64 %0, t; }"
        : "=r"(a) : "l"(p));
    return a;
}

__device__ __forceinline__ void cp16(uint32_t dst, const void* src) {
    asm volatile("cp.async.cg.shared.global [%0], [%1], 16;"
                 :: "r"(dst), "l"(src) : "memory");
}
#define CP_COMMIT() asm volatile("cp.async.commit_group;" ::: "memory")
#define CP_WAIT2()  asm volatile("cp.async.wait_group 2;"  ::: "memory")

__device__ __forceinline__ void mma16(float* c, const uint32_t* a, const uint32_t* b) {
    asm volatile(
        "mma.sync.aligned.m16n8k16.row.col.f32.f16.f16.f32 "
        "{%0,%1,%2,%3}, {%4,%5,%6,%7}, {%8,%9}, {%0,%1,%2,%3};\n"
        : "+f"(c[0]), "+f"(c[1]), "+f"(c[2]), "+f"(c[3])
        : "r"(a[0]), "r"(a[1]), "r"(a[2]), "r"(a[3]),
          "r"(b[0]), "r"(b[1]));
}

// ------------------------------ GEMM ---------------------------------------
// C[M,N] = A[M,K] * WT[N,K]^T, fp16 operands, fp32 accum, fp16 output.
// CTA 128(M) x 160(N), BK=32 halves. 256 threads = 8 warps, grid 2(m) x 4(n),
// warp tile 64x40. 4-stage cp.async pipeline. No edge guards (shapes divide).
#define BM 128
#define BN 160
#define BK 32                       // halves per k-tile
#define ROW_W 20                    // 16 data words + 4 pad (32-bit words)
#define ROW_B 80                    // bytes per smem row
#define NROWS (BM + BN)             // 288
#define STAGE_BYTES (NROWS * ROW_B) // 23040
#define NSTAGE 4
#define GEMM_SMEM (NSTAGE * STAGE_BYTES)  // 92160

__global__ void __launch_bounds__(256, 2)
gemm_h(const __half* __restrict__ A, const __half* __restrict__ BT,
       __half* __restrict__ C, int Kp, int Ndim, int KT)
{
    extern __shared__ char smraw[];
    const uint32_t sbase = smem_u32(smraw);

    const int tid  = threadIdx.x;
    const int warp = tid >> 5, lane = tid & 31;
    const int wm = warp >> 2, wn = warp & 3;      // 2(m) x 4(n)
    const int g = lane >> 2, t = lane & 3;

    const int bm = blockIdx.y * BM;
    const int bn = blockIdx.x * BN;

    float acc[4][5][4];
    #pragma unroll
    for (int i = 0; i < 4; i++)
        #pragma unroll
        for (int j = 0; j < 5; j++)
            #pragma unroll
            for (int q = 0; q < 4; q++) acc[i][j][q] = 0.f;

    // stage loader: 288 rows x 4 chunks of 16B = 1152 cp.async, 256 threads
    auto load_stage = [&](int kt, int st) {
        const int k0 = kt * BK;                   // in halves
        const uint32_t sd = sbase + st * STAGE_BYTES;
        #pragma unroll
        for (int i = 0; i < 5; i++) {
            int idx = tid + i * 256;
            if (idx < NROWS * 4) {
                int row = idx >> 2, c = idx & 3;
                const __half* src = (row < BM)
                    ? A  + (size_t)(bm + row) * Kp + k0 + c * 8
                    : BT + (size_t)(bn + (row - BM)) * Kp + k0 + c * 8;
                cp16(sd + row * ROW_B + c * 16, src);
            }
        }
    };

    load_stage(0, 0); CP_COMMIT();
    load_stage(1, 1); CP_COMMIT();
    load_stage(2, 2); CP_COMMIT();

    for (int kt = 0; kt < KT; kt++) {
        CP_WAIT2();                 // stage kt resident
        __syncthreads();            // all threads done with stage (kt+3)%4's old data
        if (kt + 3 < KT) load_stage(kt + 3, (kt + 3) & 3);
        CP_COMMIT();

        const uint32_t* As = (const uint32_t*)(smraw + (kt & 3) * STAGE_BYTES);
        const uint32_t* Bs = As + BM * ROW_W;

        #pragma unroll
        for (int ks = 0; ks < 2; ks++) {          // two k16 chunks per tile
            uint32_t af[4][4], bf[5][2];
            #pragma unroll
            for (int mf = 0; mf < 4; mf++) {
                const uint32_t* ap = As + (wm * 64 + mf * 16 + g) * ROW_W + ks * 8 + t;
                af[mf][0] = ap[0];
                af[mf][1] = ap[8 * ROW_W];
                af[mf][2] = ap[4];
                af[mf][3] = ap[8 * ROW_W + 4];
            }
            #pragma unroll
            for (int nf = 0; nf < 5; nf++) {
                const uint32_t* bp = Bs + (wn * 40 + nf * 8 + g) * ROW_W + ks * 8 + t;
                bf[nf][0] = bp[0];
                bf[nf][1] = bp[4];
            }
            #pragma unroll
            for (int mf = 0; mf < 4; mf++)
                #pragma unroll
                for (int nf = 0; nf < 5; nf++)
                    mma16(acc[mf][nf], af[mf], bf[nf]);
        }
    }

    // epilogue: fp32 acc -> half2 pairs. c0,c1 -> (row g, cols 2t,2t+1)
    #pragma unroll
    for (int mf = 0; mf < 4; mf++) {
        #pragma unroll
        for (int nf = 0; nf < 5; nf++) {
            int row0 = bm + wm * 64 + mf * 16 + g;
            int col  = bn + wn * 40 + nf * 8 + 2 * t;
            *(__half2*)&C[(size_t)row0 * Ndim + col] =
                __floats2half2_rn(acc[mf][nf][0], acc[mf][nf][1]);
            *(__half2*)&C[(size_t)(row0 + 8) * Ndim + col] =
                __floats2half2_rn(acc[mf][nf][2], acc[mf][nf][3]);
        }
    }
}

// --------------------- W transpose (fp32 -> fp16, K-major) -----------------
__global__ void transpose_h(const float* __restrict__ W, __half* __restrict__ WT,
                            int K, int N, int Kp)
{
    __shared__ float t[32][33];
    int kb = blockIdx.y * 32, nb = blockIdx.x * 32;
    #pragma unroll
    for (int i = 0; i < 32; i += 8) {
        int k = kb + threadIdx.y + i, n = nb + threadIdx.x;
        t[threadIdx.y + i][threadIdx.x] =
            (k < K && n < N) ? W[(size_t)k * N + n] : 0.f;
    }
    __syncthreads();
    #pragma unroll
    for (int i = 0; i < 32; i += 8) {
        int n = nb + threadIdx.y + i, k = kb + threadIdx.x;
        if (n < N && k < Kp)
            WT[(size_t)n * Kp + k] = __float2half_rn(t[threadIdx.x][threadIdx.y + i]);
    }
}

// --------------------------- embedding gather ------------------------------
__global__ void gather_k(const int* __restrict__ tok, const float* __restrict__ emb,
                         __half* __restrict__ X)
{
    int i = blockIdx.x * 256 + threadIdx.x;
    if (i < MROWS * KP0) {
        int m = i / KP0;
        int k = i - m * KP0;
        X[i] = (k < KDIM) ? __float2half_rn(emb[(size_t)tok[m] * KDIM + k])
                          : __half(0.f);
    }
}

// ------------------------------- SRU scans ---------------------------------
__device__ __forceinline__ float sigm(float x) { return 1.f / (1.f + __expf(-x)); }

// Layer 0: U has 4 planes [z, f, r, skip]
__global__ void scan4_k(const __half* __restrict__ U, const float* __restrict__ bias,
                        __half* __restrict__ H)
{
    int idx = blockIdx.x * blockDim.x + threadIdx.x;
    if (idx >= BATCH * DDIM) return;
    int b = idx / DDIM, d = idx - b * DDIM;
    float bf = bias[d], br = bias[DDIM + d];
    float c = 0.f;
    for (int l = 0; l < L_SEQ; l++) {
        const __half* row = U + ((size_t)(l * BATCH + b) * 4) * DDIM + d;
        float z = __half2float(row[0]);
        float f = sigm(__half2float(row[DDIM]) + bf);
        float r = sigm(__half2float(row[2 * DDIM]) + br);
        float s = __half2float(row[3 * DDIM]);
        c = f * c + (1.f - f) * z;
        H[(size_t)(l * BATCH + b) * DDIM + d] =
            __float2half_rn(r * tanhf(c) + (1.f - r) * s);
    }
}

// Layers 1-3: U has 3 planes [z, f, r]; skip = layer input
__global__ void scan3_k(const __half* __restrict__ U, const __half* __restrict__ Xin,
                        const float* __restrict__ bias, __half* __restrict__ H)
{
    int idx = blockIdx.x * blockDim.x + threadIdx.x;
    if (idx >= BATCH * DDIM) return;
    int b = idx / DDIM, d = idx - b * DDIM;
    float bf = bias[d], br = bias[DDIM + d];
    float c = 0.f;
    for (int l = 0; l < L_SEQ; l++) {
        size_t m = (size_t)(l * BATCH + b);
        const __half* row = U + m * 3 * DDIM + d;
        float z = __half2float(row[0]);
        float f = sigm(__half2float(row[DDIM]) + bf);
        float r = sigm(__half2float(row[2 * DDIM]) + br);
        float s = __half2float(Xin[m * DDIM + d]);
        c = f * c + (1.f - f) * z;
        H[m * DDIM + d] = __float2half_rn(r * tanhf(c) + (1.f - r) * s);
    }
}

// ------------------------------ L2 normalize -------------------------------
__global__ void l2norm_k(const __half* __restrict__ X, float* __restrict__ out)
{
    int row = blockIdx.x;
    const __half* x = X + (size_t)row * DDIM;
    float s = 0.f;
    for (int d = threadIdx.x; d < DDIM; d += blockDim.x) {
        float v = __half2float(x[d]);
        s += v * v;
    }
    __shared__ float sh[32];
    #pragma unroll
    for (int o = 16; o; o >>= 1) s += __shfl_xor_sync(0xffffffffu, s, o);
    int lane = threadIdx.x & 31, w = threadIdx.x >> 5;
    if (lane == 0) sh[w] = s;
    __syncthreads();
    if (w == 0) {
        s = (lane < (int)(blockDim.x >> 5)) ? sh[lane] : 0.f;
        #pragma unroll
        for (int o = 16; o; o >>= 1) s += __shfl_xor_sync(0xffffffffu, s, o);
        if (lane == 0) sh[0] = rsqrtf(s);
    }
    __syncthreads();
    float inv = sh[0];
    for (int d = threadIdx.x; d < DDIM; d += blockDim.x)
        out[(size_t)row * DDIM + d] = __half2float(x[d]) * inv;
}

// ------------------------------- launcher ----------------------------------
extern "C" void kernel_launch(void* const* d_in, const int* in_sizes, int n_in,
                              void* d_out, int out_size)
{
    const int*   tokens = (const int*)  d_in[0];
    const float* emb    = (const float*)d_in[1];
    const float* W0     = (const float*)d_in[2];
    const float* b0     = (const float*)d_in[3];
    const float* W1     = (const float*)d_in[4];
    const float* b1     = (const float*)d_in[5];
    const float* W2     = (const float*)d_in[6];
    const float* b2     = (const float*)d_in[7];
    const float* W3     = (const float*)d_in[8];
    const float* b3     = (const float*)d_in[9];
    float* out = (float*)d_out;

    __half *X0, *U, *H0, *H1, *WT0, *WT1, *WT2, *WT3;
    cudaGetSymbolAddress((void**)&X0,  g_X0h);
    cudaGetSymbolAddress((void**)&U,   g_U);
    cudaGetSymbolAddress((void**)&H0,  g_H0h);
    cudaGetSymbolAddress((void**)&H1,  g_H1h);
    cudaGetSymbolAddress((void**)&WT0, g_WT0);
    cudaGetSymbolAddress((void**)&WT1, g_WT1);
    cudaGetSymbolAddress((void**)&WT2, g_WT2);
    cudaGetSymbolAddress((void**)&WT3, g_WT3);

    cudaFuncSetAttribute(gemm_h, cudaFuncAttributeMaxDynamicSharedMemorySize,
                         GEMM_SMEM);

    // W transposes (K-major fp16, zero-padded K for layer 0)
    {
        dim3 blk(32, 8);
        transpose_h<<<dim3((N0 + 31) / 32, (KP0 + 31) / 32), blk>>>(W0, WT0, KDIM, N0, KP0);
        transpose_h<<<dim3((N123 + 31) / 32, (DDIM + 31) / 32), blk>>>(W1, WT1, DDIM, N123, DDIM);
        transpose_h<<<dim3((N123 + 31) / 32, (DDIM + 31) / 32), blk>>>(W2, WT2, DDIM, N123, DDIM);
        transpose_h<<<dim3((N123 + 31) / 32, (DDIM + 31) / 32), blk>>>(W3, WT3, DDIM, N123, DDIM);
    }

    // Embedding gather (fp16, padded rows)
    gather_k<<<(MROWS * KP0 + 255) / 256, 256>>>(tokens, emb, X0);

    const int scan_blocks = (BATCH * DDIM + 255) / 256;
    const int KT0 = KP0 / BK;    // 20
    const int KT1 = DDIM / BK;   // 75

    // Layer 0: K=640(pad), N=9600
    gemm_h<<<dim3(N0 / BN, MROWS / BM), 256, GEMM_SMEM>>>(X0, WT0, U, KP0, N0, KT0);
    scan4_k<<<scan_blocks, 256>>>(U, b0, H0);

    // Layer 1
    gemm_h<<<dim3(N123 / BN, MROWS / BM), 256, GEMM_SMEM>>>(H0, WT1, U, DDIM, N123, KT1);
    scan3_k<<<scan_blocks, 256>>>(U, H0, b1, H1);

    // Layer 2
    gemm_h<<<dim3(N123 / BN, MROWS / BM), 256, GEMM_SMEM>>>(H1, WT2, U, DDIM, N123, KT1);
    scan3_k<<<scan_blocks, 256>>>(U, H1, b2, H0);

    // Layer 3
    gemm_h<<<dim3(N123 / BN, MROWS / BM), 256, GEMM_SMEM>>>(H0, WT3, U, DDIM, N123, KT1);
    scan3_k<<<scan_blocks, 256>>>(U, H0, b3, H1);

    // Final L2 normalization -> d_out (fp32)
    l2norm_k<<<MROWS, 256>>>(H1, out);
}